// round 13
// baseline (speedup 1.0000x reference)
#include <cuda_runtime.h>
#include <cuda_fp16.h>
#include <cstdint>

#define D_MODEL   1024
#define NUM_HEADS 16
#define SEQ       2048
#define BATCH     2
#define MTOT      (BATCH*SEQ)   /* 4096 */
#define LOG2E     1.4426950408889634f

// Scratch (allocation-free rule: __device__ globals).
__device__ __half h_q[(size_t)MTOT * D_MODEL];
__device__ __half h_k[(size_t)MTOT * D_MODEL];
__device__ __half h_v[(size_t)MTOT * D_MODEL];
__device__ __half h_wq[(size_t)D_MODEL * D_MODEL];
__device__ __half h_wk[(size_t)D_MODEL * D_MODEL];
__device__ __half h_wv[(size_t)D_MODEL * D_MODEL];
__device__ __half h_wo[(size_t)D_MODEL * D_MODEL];
__device__ __half g_Q[(size_t)MTOT * D_MODEL];   // [b,h,s,d], pre-scaled by 0.125*log2e
__device__ __half g_K[(size_t)MTOT * D_MODEL];   // [b,h,s,d]
__device__ __half g_V[(size_t)MTOT * D_MODEL];   // TRANSPOSED [b,h,d,s]
__device__ __half g_ctx[(size_t)MTOT * D_MODEL]; // [m, D_MODEL] fp16

__device__ __forceinline__ void ldsm4(unsigned& r0, unsigned& r1, unsigned& r2, unsigned& r3,
                                      const void* p) {
    unsigned a = (unsigned)__cvta_generic_to_shared(p);
    asm volatile("ldmatrix.sync.aligned.m8n8.x4.shared.b16 {%0,%1,%2,%3}, [%4];"
                 : "=r"(r0), "=r"(r1), "=r"(r2), "=r"(r3) : "r"(a));
}
__device__ __forceinline__ void mma16(float* c, unsigned a0, unsigned a1, unsigned a2, unsigned a3,
                                      unsigned b0, unsigned b1) {
    asm volatile("mma.sync.aligned.m16n8k16.row.col.f32.f16.f16.f32 "
                 "{%0,%1,%2,%3},{%4,%5,%6,%7},{%8,%9},{%0,%1,%2,%3};"
                 : "+f"(c[0]), "+f"(c[1]), "+f"(c[2]), "+f"(c[3])
                 : "r"(a0), "r"(a1), "r"(a2), "r"(a3), "r"(b0), "r"(b1));
}
__device__ __forceinline__ void cp16(void* smem_dst, const void* gsrc) {
    unsigned d = (unsigned)__cvta_generic_to_shared(smem_dst);
    asm volatile("cp.async.cg.shared.global [%0], [%1], 16;\n" :: "r"(d), "l"(gsrc));
}
__device__ __forceinline__ void cp_commit() { asm volatile("cp.async.commit_group;\n"); }
template <int N> __device__ __forceinline__ void cp_wait() {
    asm volatile("cp.async.wait_group %0;\n" :: "n"(N));
}

// ------------------------- fp32 -> fp16 conversion (7 tensors, one launch) ----
struct CvtJobs { const float* src[7]; __half* dst[7]; int n[7]; };

__global__ __launch_bounds__(256) void cvt_f16(CvtJobs jobs)
{
    int j = blockIdx.y;
    int base = (blockIdx.x * 256 + threadIdx.x) * 8;
    if (base >= jobs.n[j]) return;
    const float4* s = (const float4*)(jobs.src[j] + base);
    float4 v0 = s[0], v1 = s[1];
    __half2 p0 = __floats2half2_rn(v0.x, v0.y);
    __half2 p1 = __floats2half2_rn(v0.z, v0.w);
    __half2 p2 = __floats2half2_rn(v1.x, v1.y);
    __half2 p3 = __floats2half2_rn(v1.z, v1.w);
    uint4 u; u.x = *(unsigned*)&p0; u.y = *(unsigned*)&p1;
    u.z = *(unsigned*)&p2; u.w = *(unsigned*)&p3;
    *(uint4*)(jobs.dst[j] + base) = u;
}

// --------- fp16 GEMM: 256x128 CTA tile, 512 threads (16 warps of 32x64) -------
// C = A * W^T + bias. 4-stage cp.async pipeline, k-chunk 32.
// mode 0: fp32 [m,n]; mode 1: fp16 headsplit [b,h,s,d] (*oscale);
// mode 2: fp16 headsplit TRANSPOSED [b,h,d,s]
#define KGP 40                       /* smem pitch halves: 32 + 8 */
#define GSTG_A (256 * KGP)           /* 10240 halves */
#define GSTG_B (128 * KGP)           /* 5120 halves  */
#define GSTAGE_H (GSTG_A + GSTG_B)   /* 15360 halves */
#define NSTAGE 4
#define GCHUNKS 32                   /* 1024 / 32 */
#define GEMM_SMEM_BYTES (NSTAGE * GSTAGE_H * 2)   /* 122880 */

struct GemmJob { const __half* A; const __half* W; const float* bias;
                 void* C; int mode; float oscale; };
struct GemmJobs3 { GemmJob j[3]; };

__global__ __launch_bounds__(512, 1) void gemm_f16p(GemmJobs3 js)
{
    extern __shared__ __half sg[];
    const GemmJob jb = js.j[blockIdx.z];
    const int t = threadIdx.x, lane = t & 31, warp = t >> 5;
    const int wm = warp >> 1, wn = warp & 1;     // 8 x 2 warp grid, 32x64 each
    const int g = lane >> 2, tt = lane & 3;
    const int bm = blockIdx.x, bn = blockIdx.y;

    float acc[2][8][4];
#pragma unroll
    for (int mt = 0; mt < 2; mt++)
#pragma unroll
        for (int nt = 0; nt < 8; nt++)
#pragma unroll
            for (int i = 0; i < 4; i++) acc[mt][nt][i] = 0.f;

    const __half* Ap = jb.A + (size_t)bm * 256 * 1024;
    const __half* Wp = jb.W + (size_t)bn * 128 * 1024;

    const int a_row  = (lane & 7) + ((lane & 8) ? 8 : 0);
    const int a_col8 = (lane & 16) ? 8 : 0;
    const int b_row  = (lane & 7) + ((lane & 16) ? 8 : 0);
    const int b_col8 = (lane & 8) ? 8 : 0;

    // fill mapping: A 1024 cp16 slots (2/thread), B 512 slots (1/thread)
    const int far0 = t >> 2,        fac0 = (t & 3) * 8;
    const int far1 = (t + 512) >> 2, fac1 = ((t + 512) & 3) * 8;
    const int fbr  = t >> 2,        fbc  = (t & 3) * 8;   // t<512 -> rows 0..127

    // prologue: stages 0..2
#pragma unroll
    for (int st = 0; st < NSTAGE - 1; st++) {
        __half* Sa = sg + st * GSTAGE_H;
        __half* Sb = Sa + GSTG_A;
        int k0 = st * 32;
        cp16(&Sa[far0 * KGP + fac0], Ap + (size_t)far0 * 1024 + k0 + fac0);
        cp16(&Sa[far1 * KGP + fac1], Ap + (size_t)far1 * 1024 + k0 + fac1);
        cp16(&Sb[fbr  * KGP + fbc ], Wp + (size_t)fbr  * 1024 + k0 + fbc);
        cp_commit();
    }

    for (int ks = 0; ks < GCHUNKS; ks++) {
        cp_wait<2>();
        __syncthreads();

        if (ks + 3 < GCHUNKS) {
            int st = (ks + 3) & 3;
            __half* Sa = sg + st * GSTAGE_H;
            __half* Sb = Sa + GSTG_A;
            int k0 = (ks + 3) * 32;
            cp16(&Sa[far0 * KGP + fac0], Ap + (size_t)far0 * 1024 + k0 + fac0);
            cp16(&Sa[far1 * KGP + fac1], Ap + (size_t)far1 * 1024 + k0 + fac1);
            cp16(&Sb[fbr  * KGP + fbc ], Wp + (size_t)fbr  * 1024 + k0 + fbc);
        }
        cp_commit();

        __half* Sa = sg + (ks & 3) * GSTAGE_H;
        __half* Sb = Sa + GSTG_A;
#pragma unroll
        for (int kq = 0; kq < 32; kq += 16) {
            unsigned a[2][4];
#pragma unroll
            for (int mt = 0; mt < 2; mt++) {
                int base = wm * 32 + mt * 16;
                ldsm4(a[mt][0], a[mt][1], a[mt][2], a[mt][3],
                      &Sa[(base + a_row) * KGP + kq + a_col8]);
            }
            unsigned b[8][2];
#pragma unroll
            for (int np = 0; np < 4; np++) {
                int nb = wn * 64 + np * 16;
                ldsm4(b[np * 2][0], b[np * 2][1], b[np * 2 + 1][0], b[np * 2 + 1][1],
                      &Sb[(nb + b_row) * KGP + kq + b_col8]);
            }
#pragma unroll
            for (int mt = 0; mt < 2; mt++)
#pragma unroll
                for (int nt = 0; nt < 8; nt++)
                    mma16(acc[mt][nt], a[mt][0], a[mt][1], a[mt][2], a[mt][3],
                          b[nt][0], b[nt][1]);
        }
    }

#pragma unroll
    for (int mt = 0; mt < 2; mt++) {
        int row0 = bm * 256 + wm * 32 + mt * 16 + g;
#pragma unroll
        for (int nt = 0; nt < 8; nt++) {
            int cc = bn * 128 + wn * 64 + nt * 8 + 2 * tt;
            float2 bb = *(const float2*)&jb.bias[cc];
#pragma unroll
            for (int rp = 0; rp < 2; rp++) {
                int row = row0 + rp * 8;
                float2 v;
                v.x = acc[mt][nt][rp * 2 + 0] + bb.x;
                v.y = acc[mt][nt][rp * 2 + 1] + bb.y;
                int b = row >> 11, sq = row & (SEQ - 1);
                int h = cc >> 6, dd = cc & 63;
                if (jb.mode == 1) {
                    __half* C = (__half*)jb.C;
                    __half2 hv = __floats2half2_rn(v.x * jb.oscale, v.y * jb.oscale);
                    *(__half2*)&C[((size_t)((b * NUM_HEADS + h) * SEQ + sq) << 6) + dd] = hv;
                } else if (jb.mode == 2) {
                    __half* C = (__half*)jb.C;
                    size_t base = (size_t)((b * NUM_HEADS + h) * 64 + dd) * SEQ + sq;
                    C[base] = __float2half_rn(v.x);
                    C[base + SEQ] = __float2half_rn(v.y);
                } else {
                    float* C = (float*)jb.C;
                    *(float2*)&C[(size_t)row * D_MODEL + cc] = v;
                }
            }
        }
    }
}

// ------------------------- flash attention, fp16 mma -------------------------
// 128 threads (4 warps), warp owns 32 q rows (2 m-frags) -> Br=128, 2 CTAs/SM.
#define KPH 72
#define VPH 136
#define PPH 72
#define KS_H (128 * KPH)
#define VT_H (64 * VPH)
#define P_H  (32 * PPH)
#define ATTN_SMEM_BYTES ((2 * KS_H + 2 * VT_H + 4 * P_H) * 2)  /* 90112 */

__global__ __launch_bounds__(128, 2) void attn_f16()
{
    extern __shared__ __half smh[];
    __half* const Ksm0 = smh;
    __half* const Ksm1 = smh + KS_H;
    __half* const Vsm0 = smh + 2 * KS_H;
    __half* const Vsm1 = smh + 2 * KS_H + VT_H;

    const int t = threadIdx.x, lane = t & 31, warp = t >> 5;
    const int g = lane >> 2, tt = lane & 3;
    const int qt = blockIdx.x;
    const int bh = blockIdx.y;

    __half* const Pw = smh + 2 * KS_H + 2 * VT_H + warp * P_H;

    const __half* Qb  = g_Q + ((size_t)bh * SEQ + qt * 128) * 64;
    const __half* Kb  = g_K + (size_t)bh * SEQ * 64;
    const __half* Vtb = g_V + (size_t)bh * 64 * SEQ;

    unsigned Qf[4][2][4];
    const int qr = warp * 32;
#pragma unroll
    for (int dq = 0; dq < 4; dq++)
#pragma unroll
        for (int mt = 0; mt < 2; mt++) {
            int r0 = qr + mt * 16 + g;
            Qf[dq][mt][0] = *(const unsigned*)(Qb + r0       * 64 + dq * 16 + 2 * tt);
            Qf[dq][mt][1] = *(const unsigned*)(Qb + (r0 + 8) * 64 + dq * 16 + 2 * tt);
            Qf[dq][mt][2] = *(const unsigned*)(Qb + r0       * 64 + dq * 16 + 8 + 2 * tt);
            Qf[dq][mt][3] = *(const unsigned*)(Qb + (r0 + 8) * 64 + dq * 16 + 8 + 2 * tt);
        }

    float Of[2][8][4];
#pragma unroll
    for (int mt = 0; mt < 2; mt++)
#pragma unroll
        for (int nt = 0; nt < 8; nt++)
#pragma unroll
            for (int i = 0; i < 4; i++) Of[mt][nt][i] = 0.f;
    float mrow[2][2] = {{-1e30f, -1e30f}, {-1e30f, -1e30f}};
    float lrow[2][2] = {{0.f, 0.f}, {0.f, 0.f}};

    const int a_row  = (lane & 7) + ((lane & 8) ? 8 : 0);
    const int a_col8 = (lane & 16) ? 8 : 0;
    const int b_row  = (lane & 7) + ((lane & 16) ? 8 : 0);
    const int b_col8 = (lane & 8) ? 8 : 0;

    {
#pragma unroll
        for (int l = 0; l < 8; l++) {
            int s = t + 128 * l;
            int kr = s >> 3, kc = (s & 7) * 8;
            cp16(&Ksm0[kr * KPH + kc], Kb + (size_t)kr * 64 + kc);
            int vr = s >> 4, vc = (s & 15) * 8;
            cp16(&Vsm0[vr * VPH + vc], Vtb + (size_t)vr * SEQ + vc);
        }
        cp_commit();
    }

    for (int kt = 0; kt < SEQ / 128; kt++) {
        __half* const Kcur = (kt & 1) ? Ksm1 : Ksm0;
        __half* const Vcur = (kt & 1) ? Vsm1 : Vsm0;
        __half* const Knxt = (kt & 1) ? Ksm0 : Ksm1;
        __half* const Vnxt = (kt & 1) ? Vsm0 : Vsm1;

        cp_wait<0>();
        __syncthreads();

        if (kt < SEQ / 128 - 1) {
            const __half* Kp = Kb + (size_t)(kt + 1) * 128 * 64;
            const __half* Vp = Vtb + (kt + 1) * 128;
#pragma unroll
            for (int l = 0; l < 8; l++) {
                int s = t + 128 * l;
                int kr = s >> 3, kc = (s & 7) * 8;
                cp16(&Knxt[kr * KPH + kc], Kp + (size_t)kr * 64 + kc);
                int vr = s >> 4, vc = (s & 15) * 8;
                cp16(&Vnxt[vr * VPH + vc], Vp + (size_t)vr * SEQ + vc);
            }
            cp_commit();
        }

#pragma unroll
        for (int hf = 0; hf < 2; hf++) {
            const int hk = hf * 64;

            float sf[2][8][4];
#pragma unroll
            for (int mt = 0; mt < 2; mt++)
#pragma unroll
                for (int nt = 0; nt < 8; nt++)
#pragma unroll
                    for (int i = 0; i < 4; i++) sf[mt][nt][i] = 0.f;

#pragma unroll
            for (int dq = 0; dq < 4; dq++) {
                unsigned b[8][2];
#pragma unroll
                for (int np = 0; np < 4; np++)
                    ldsm4(b[np * 2][0], b[np * 2][1], b[np * 2 + 1][0], b[np * 2 + 1][1],
                          &Kcur[(hk + np * 16 + b_row) * KPH + dq * 16 + b_col8]);
#pragma unroll
                for (int mt = 0; mt < 2; mt++)
#pragma unroll
                    for (int nt = 0; nt < 8; nt++)
                        mma16(sf[mt][nt], Qf[dq][mt][0], Qf[dq][mt][1],
                              Qf[dq][mt][2], Qf[dq][mt][3], b[nt][0], b[nt][1]);
            }

#pragma unroll
            for (int mt = 0; mt < 2; mt++) {
                float alpha[2];
#pragma unroll
                for (int rp = 0; rp < 2; rp++) {
                    float mx = -1e30f;
#pragma unroll
                    for (int nt = 0; nt < 8; nt++)
                        mx = fmaxf(mx, fmaxf(sf[mt][nt][rp * 2], sf[mt][nt][rp * 2 + 1]));
                    mx = fmaxf(mx, __shfl_xor_sync(0xffffffffu, mx, 1));
                    mx = fmaxf(mx, __shfl_xor_sync(0xffffffffu, mx, 2));
                    float nm = fmaxf(mrow[mt][rp], mx);
                    float sum = 0.f;
#pragma unroll
                    for (int nt = 0; nt < 8; nt++) {
                        float p0 = exp2f(sf[mt][nt][rp * 2]     - nm);
                        float p1 = exp2f(sf[mt][nt][rp * 2 + 1] - nm);
                        sf[mt][nt][rp * 2] = p0; sf[mt][nt][rp * 2 + 1] = p1;
                        sum += p0 + p1;
                    }
                    sum += __shfl_xor_sync(0xffffffffu, sum, 1);
                    sum += __shfl_xor_sync(0xffffffffu, sum, 2);
                    alpha[rp] = exp2f(mrow[mt][rp] - nm);
                    mrow[mt][rp] = nm;
                    lrow[mt][rp] = lrow[mt][rp] * alpha[rp] + sum;
                }
#pragma unroll
                for (int nt = 0; nt < 8; nt++) {
                    Of[mt][nt][0] *= alpha[0]; Of[mt][nt][1] *= alpha[0];
                    Of[mt][nt][2] *= alpha[1]; Of[mt][nt][3] *= alpha[1];
                }
            }

            __syncwarp();
#pragma unroll
            for (int mt = 0; mt < 2; mt++)
#pragma unroll
                for (int nt = 0; nt < 8; nt++) {
                    __half2 h0 = __floats2half2_rn(sf[mt][nt][0], sf[mt][nt][1]);
                    __half2 h1 = __floats2half2_rn(sf[mt][nt][2], sf[mt][nt][3]);
                    *(__half2*)&Pw[(mt * 16 + g)     * PPH + nt * 8 + 2 * tt] = h0;
                    *(__half2*)&Pw[(mt * 16 + g + 8) * PPH + nt * 8 + 2 * tt] = h1;
                }
            __syncwarp();

#pragma unroll
            for (int kq = 0; kq < 4; kq++) {
                unsigned a[2][4];
#pragma unroll
                for (int mt = 0; mt < 2; mt++)
                    ldsm4(a[mt][0], a[mt][1], a[mt][2], a[mt][3],
                          &Pw[(mt * 16 + a_row) * PPH + kq * 16 + a_col8]);
                unsigned vb[8][2];
#pragma unroll
                for (int np = 0; np < 4; np++)
                    ldsm4(vb[np * 2][0], vb[np * 2][1], vb[np * 2 + 1][0], vb[np * 2 + 1][1],
                          &Vcur[(np * 16 + b_row) * VPH + hk + kq * 16 + b_col8]);
#pragma unroll
                for (int mt = 0; mt < 2; mt++)
#pragma unroll
                    for (int nt = 0; nt < 8; nt++)
                        mma16(Of[mt][nt], a[mt][0], a[mt][1], a[mt][2], a[mt][3],
                              vb[nt][0], vb[nt][1]);
            }
        }
        __syncthreads();
    }

    const int b = bh >> 4, h = bh & 15;
#pragma unroll
    for (int mt = 0; mt < 2; mt++) {
        const float inv0 = 1.f / lrow[mt][0], inv1 = 1.f / lrow[mt][1];
        const int row = qt * 128 + warp * 32 + mt * 16 + g;
#pragma unroll
        for (int nt = 0; nt < 8; nt++) {
            size_t base  = ((size_t)(b * SEQ + row))     * D_MODEL + h * 64 + nt * 8 + 2 * tt;
            size_t base2 = ((size_t)(b * SEQ + row + 8)) * D_MODEL + h * 64 + nt * 8 + 2 * tt;
            *(__half2*)&g_ctx[base]  = __floats2half2_rn(Of[mt][nt][0] * inv0,
                                                         Of[mt][nt][1] * inv0);
            *(__half2*)&g_ctx[base2] = __floats2half2_rn(Of[mt][nt][2] * inv1,
                                                         Of[mt][nt][3] * inv1);
        }
    }
}

extern "C" void kernel_launch(void* const* d_in, const int* in_sizes, int n_in,
                              void* d_out, int out_size)
{
    const float* query = (const float*)d_in[0];
    const float* key   = (const float*)d_in[1];
    const float* value = (const float*)d_in[2];
    const float* Wq    = (const float*)d_in[3];
    const float* bq    = (const float*)d_in[4];
    const float* Wk    = (const float*)d_in[5];
    const float* bk    = (const float*)d_in[6];
    const float* Wv    = (const float*)d_in[7];
    const float* bv    = (const float*)d_in[8];
    const float* Wo    = (const float*)d_in[9];
    const float* bo    = (const float*)d_in[10];
    float* out = (float*)d_out;

    __half *hq, *hk, *hv, *hwq, *hwk, *hwv, *hwo, *gQ, *gK, *gV, *gC;
    cudaGetSymbolAddress((void**)&hq,  h_q);
    cudaGetSymbolAddress((void**)&hk,  h_k);
    cudaGetSymbolAddress((void**)&hv,  h_v);
    cudaGetSymbolAddress((void**)&hwq, h_wq);
    cudaGetSymbolAddress((void**)&hwk, h_wk);
    cudaGetSymbolAddress((void**)&hwv, h_wv);
    cudaGetSymbolAddress((void**)&hwo, h_wo);
    cudaGetSymbolAddress((void**)&gQ,  g_Q);
    cudaGetSymbolAddress((void**)&gK,  g_K);
    cudaGetSymbolAddress((void**)&gV,  g_V);
    cudaGetSymbolAddress((void**)&gC,  g_ctx);

    cudaFuncSetAttribute(attn_f16, cudaFuncAttributeMaxDynamicSharedMemorySize,
                         ATTN_SMEM_BYTES);
    cudaFuncSetAttribute(gemm_f16p, cudaFuncAttributeMaxDynamicSharedMemorySize,
                         GEMM_SMEM_BYTES);

    // 1) convert everything to fp16 (one launch)
    CvtJobs cj;
    cj.src[0] = query; cj.dst[0] = hq;  cj.n[0] = MTOT * D_MODEL;
    cj.src[1] = key;   cj.dst[1] = hk;  cj.n[1] = MTOT * D_MODEL;
    cj.src[2] = value; cj.dst[2] = hv;  cj.n[2] = MTOT * D_MODEL;
    cj.src[3] = Wq;    cj.dst[3] = hwq; cj.n[3] = D_MODEL * D_MODEL;
    cj.src[4] = Wk;    cj.dst[4] = hwk; cj.n[4] = D_MODEL * D_MODEL;
    cj.src[5] = Wv;    cj.dst[5] = hwv; cj.n[5] = D_MODEL * D_MODEL;
    cj.src[6] = Wo;    cj.dst[6] = hwo; cj.n[6] = D_MODEL * D_MODEL;
    cvt_f16<<<dim3(MTOT * D_MODEL / (256 * 8), 7), 256>>>(cj);

    // 2) fused Q/K/V projections (M-tile 256)
    GemmJobs3 qkv;
    qkv.j[0] = { hq, hwq, bq, gQ, 1, 0.125f * LOG2E };
    qkv.j[1] = { hk, hwk, bk, gK, 1, 1.0f };
    qkv.j[2] = { hv, hwv, bv, gV, 2, 1.0f };
    gemm_f16p<<<dim3(MTOT / 256, D_MODEL / 128, 3), 512, GEMM_SMEM_BYTES>>>(qkv);

    // 3) attention (Br=128, 4 warps x 32 q rows)
    dim3 agrid(SEQ / 128, BATCH * NUM_HEADS);
    attn_f16<<<agrid, 128, ATTN_SMEM_BYTES>>>();

    // 4) output projection
    GemmJobs3 oj;
    oj.j[0] = { gC, hwo, bo, out, 0, 1.0f };
    oj.j[1] = oj.j[0]; oj.j[2] = oj.j[0];
    gemm_f16p<<<dim3(MTOT / 256, D_MODEL / 128, 1), 512, GEMM_SMEM_BYTES>>>(oj);
}

// round 15
// speedup vs baseline: 1.4975x; 1.4975x over previous
#include <cuda_runtime.h>
#include <cuda_fp16.h>
#include <cstdint>

#define D_MODEL   1024
#define NUM_HEADS 16
#define SEQ       2048
#define BATCH     2
#define MTOT      (BATCH*SEQ)   /* 4096 */
#define LOG2E     1.4426950408889634f

// Scratch (allocation-free rule: __device__ globals).
__device__ __half h_q[(size_t)MTOT * D_MODEL];
__device__ __half h_k[(size_t)MTOT * D_MODEL];
__device__ __half h_v[(size_t)MTOT * D_MODEL];
__device__ __half h_wq[(size_t)D_MODEL * D_MODEL];
__device__ __half h_wk[(size_t)D_MODEL * D_MODEL];
__device__ __half h_wv[(size_t)D_MODEL * D_MODEL];
__device__ __half h_wo[(size_t)D_MODEL * D_MODEL];
__device__ __half g_Q[(size_t)MTOT * D_MODEL];   // [b,h,s,d], pre-scaled by 0.125*log2e
__device__ __half g_K[(size_t)MTOT * D_MODEL];   // [b,h,s,d]
__device__ __half g_V[(size_t)MTOT * D_MODEL];   // TRANSPOSED [b,h,d,s]
__device__ __half g_ctx[(size_t)MTOT * D_MODEL]; // [m, D_MODEL] fp16

__device__ __forceinline__ void ldsm4(unsigned& r0, unsigned& r1, unsigned& r2, unsigned& r3,
                                      const void* p) {
    unsigned a = (unsigned)__cvta_generic_to_shared(p);
    asm volatile("ldmatrix.sync.aligned.m8n8.x4.shared.b16 {%0,%1,%2,%3}, [%4];"
                 : "=r"(r0), "=r"(r1), "=r"(r2), "=r"(r3) : "r"(a));
}
__device__ __forceinline__ void mma16(float* c, unsigned a0, unsigned a1, unsigned a2, unsigned a3,
                                      unsigned b0, unsigned b1) {
    asm volatile("mma.sync.aligned.m16n8k16.row.col.f32.f16.f16.f32 "
                 "{%0,%1,%2,%3},{%4,%5,%6,%7},{%8,%9},{%0,%1,%2,%3};"
                 : "+f"(c[0]), "+f"(c[1]), "+f"(c[2]), "+f"(c[3])
                 : "r"(a0), "r"(a1), "r"(a2), "r"(a3), "r"(b0), "r"(b1));
}
__device__ __forceinline__ void cp16(void* smem_dst, const void* gsrc) {
    unsigned d = (unsigned)__cvta_generic_to_shared(smem_dst);
    asm volatile("cp.async.cg.shared.global [%0], [%1], 16;\n" :: "r"(d), "l"(gsrc));
}
__device__ __forceinline__ void cp_commit() { asm volatile("cp.async.commit_group;\n"); }
template <int N> __device__ __forceinline__ void cp_wait() {
    asm volatile("cp.async.wait_group %0;\n" :: "n"(N));
}

// ------------------------- fp32 -> fp16 conversion (7 tensors, one launch) ----
struct CvtJobs { const float* src[7]; __half* dst[7]; int n[7]; };

__global__ __launch_bounds__(256) void cvt_f16(CvtJobs jobs)
{
    int j = blockIdx.y;
    int base = (blockIdx.x * 256 + threadIdx.x) * 8;
    if (base >= jobs.n[j]) return;
    const float4* s = (const float4*)(jobs.src[j] + base);
    float4 v0 = s[0], v1 = s[1];
    __half2 p0 = __floats2half2_rn(v0.x, v0.y);
    __half2 p1 = __floats2half2_rn(v0.z, v0.w);
    __half2 p2 = __floats2half2_rn(v1.x, v1.y);
    __half2 p3 = __floats2half2_rn(v1.z, v1.w);
    uint4 u; u.x = *(unsigned*)&p0; u.y = *(unsigned*)&p1;
    u.z = *(unsigned*)&p2; u.w = *(unsigned*)&p3;
    *(uint4*)(jobs.dst[j] + base) = u;
}

// ---- fp16 GEMM: 128x128 CTA, 8 warps of 32x64 (round-11 shape), paired chunks ----
// 4 chunk-stages of k=32; one barrier per 2 chunks (k=64). 2 CTAs/SM.
// mode 0: fp32 [m,n]; mode 1: fp16 headsplit [b,h,s,d] (*oscale);
// mode 2: fp16 headsplit TRANSPOSED [b,h,d,s]
#define KGP 40                      /* smem pitch halves: 32 + 8 */
#define GSTG (128 * KGP)            /* halves per matrix per chunk: 5120 */
#define GSTAGE_H (2 * GSTG)         /* A+B per chunk: 10240 halves */
#define GEMM_SMEM_BYTES (4 * GSTAGE_H * 2)   /* 81920 */

struct GemmJob { const __half* A; const __half* W; const float* bias;
                 void* C; int mode; float oscale; };
struct GemmJobs3 { GemmJob j[3]; };

__global__ __launch_bounds__(256, 2) void gemm_f16p(GemmJobs3 js)
{
    extern __shared__ __half sg[];
    const GemmJob jb = js.j[blockIdx.z];
    const int t = threadIdx.x, lane = t & 31, warp = t >> 5;
    const int wm = warp >> 1, wn = warp & 1;
    const int g = lane >> 2, tt = lane & 3;
    const int bm = blockIdx.x, bn = blockIdx.y;

    float acc[2][8][4];
#pragma unroll
    for (int mt = 0; mt < 2; mt++)
#pragma unroll
        for (int nt = 0; nt < 8; nt++)
#pragma unroll
            for (int i = 0; i < 4; i++) acc[mt][nt][i] = 0.f;

    const __half* Ap = jb.A + (size_t)bm * 128 * 1024;
    const __half* Wp = jb.W + (size_t)bn * 128 * 1024;

    const int a_row  = (lane & 7) + ((lane & 8) ? 8 : 0);
    const int a_col8 = (lane & 16) ? 8 : 0;
    const int b_row  = (lane & 7) + ((lane & 16) ? 8 : 0);
    const int b_col8 = (lane & 8) ? 8 : 0;

    const int fm0 = t >> 2, fc0 = (t & 3) * 8;
    const int fm1 = (t + 256) >> 2, fc1 = ((t + 256) & 3) * 8;

    // fill one k=32 chunk (A+B) into stage st
#define G_FILL(ck, st) do {                                                     \
        __half* Sa_ = sg + (st) * GSTAGE_H;                                     \
        __half* Sb_ = Sa_ + GSTG;                                               \
        int k0_ = (ck) * 32;                                                    \
        cp16(&Sa_[fm0 * KGP + fc0], Ap + (size_t)fm0 * 1024 + k0_ + fc0);       \
        cp16(&Sa_[fm1 * KGP + fc1], Ap + (size_t)fm1 * 1024 + k0_ + fc1);       \
        cp16(&Sb_[fm0 * KGP + fc0], Wp + (size_t)fm0 * 1024 + k0_ + fc0);       \
        cp16(&Sb_[fm1 * KGP + fc1], Wp + (size_t)fm1 * 1024 + k0_ + fc1);       \
    } while (0)

    // prologue: pair 0 (chunks 0,1 -> stages 0,1)
    G_FILL(0, 0);
    G_FILL(1, 1);
    cp_commit();

    for (int p = 0; p < 16; p++) {
        cp_wait<0>();          // current pair resident
        __syncthreads();       // previous pair's compute done before overwrite

        if (p + 1 < 16) {      // prefetch next pair into the other pair-buffer
            int sb = ((p + 1) & 1) * 2;
            G_FILL(2 * (p + 1),     sb);
            G_FILL(2 * (p + 1) + 1, sb + 1);
            cp_commit();
        }

        // compute chunks 2p, 2p+1 from stages (p&1)*2, +1
#pragma unroll
        for (int half = 0; half < 2; half++) {
            __half* Sa = sg + ((p & 1) * 2 + half) * GSTAGE_H;
            __half* Sb = Sa + GSTG;
#pragma unroll
            for (int kq = 0; kq < 32; kq += 16) {
                unsigned a[2][4];
#pragma unroll
                for (int mt = 0; mt < 2; mt++) {
                    int base = wm * 32 + mt * 16;
                    ldsm4(a[mt][0], a[mt][1], a[mt][2], a[mt][3],
                          &Sa[(base + a_row) * KGP + kq + a_col8]);
                }
                unsigned b[8][2];
#pragma unroll
                for (int np = 0; np < 4; np++) {
                    int nb = wn * 64 + np * 16;
                    ldsm4(b[np * 2][0], b[np * 2][1], b[np * 2 + 1][0], b[np * 2 + 1][1],
                          &Sb[(nb + b_row) * KGP + kq + b_col8]);
                }
#pragma unroll
                for (int mt = 0; mt < 2; mt++)
#pragma unroll
                    for (int nt = 0; nt < 8; nt++)
                        mma16(acc[mt][nt], a[mt][0], a[mt][1], a[mt][2], a[mt][3],
                              b[nt][0], b[nt][1]);
            }
        }
    }
#undef G_FILL

#pragma unroll
    for (int mt = 0; mt < 2; mt++) {
        int row0 = bm * 128 + wm * 32 + mt * 16 + g;
#pragma unroll
        for (int nt = 0; nt < 8; nt++) {
            int cc = bn * 128 + wn * 64 + nt * 8 + 2 * tt;
            float2 bb = *(const float2*)&jb.bias[cc];
#pragma unroll
            for (int rp = 0; rp < 2; rp++) {
                int row = row0 + rp * 8;
                float2 v;
                v.x = acc[mt][nt][rp * 2 + 0] + bb.x;
                v.y = acc[mt][nt][rp * 2 + 1] + bb.y;
                int b = row >> 11, sq = row & (SEQ - 1);
                int h = cc >> 6, dd = cc & 63;
                if (jb.mode == 1) {
                    __half* C = (__half*)jb.C;
                    __half2 hv = __floats2half2_rn(v.x * jb.oscale, v.y * jb.oscale);
                    *(__half2*)&C[((size_t)((b * NUM_HEADS + h) * SEQ + sq) << 6) + dd] = hv;
                } else if (jb.mode == 2) {
                    __half* C = (__half*)jb.C;
                    size_t base = (size_t)((b * NUM_HEADS + h) * 64 + dd) * SEQ + sq;
                    C[base] = __float2half_rn(v.x);
                    C[base + SEQ] = __float2half_rn(v.y);
                } else {
                    float* C = (float*)jb.C;
                    *(float2*)&C[(size_t)row * D_MODEL + cc] = v;
                }
            }
        }
    }
}

// ------------------------- flash attention, fp16 mma -------------------------
// 128 threads (4 warps), warp owns 32 q rows (2 m-frags) -> Br=128, 2 CTAs/SM.
#define KPH 72
#define VPH 136
#define PPH 72
#define KS_H (128 * KPH)
#define VT_H (64 * VPH)
#define P_H  (32 * PPH)
#define ATTN_SMEM_BYTES ((2 * KS_H + 2 * VT_H + 4 * P_H) * 2)  /* 90112 */

__global__ __launch_bounds__(128, 2) void attn_f16()
{
    extern __shared__ __half smh[];
    __half* const Ksm0 = smh;
    __half* const Ksm1 = smh + KS_H;
    __half* const Vsm0 = smh + 2 * KS_H;
    __half* const Vsm1 = smh + 2 * KS_H + VT_H;

    const int t = threadIdx.x, lane = t & 31, warp = t >> 5;
    const int g = lane >> 2, tt = lane & 3;
    const int qt = blockIdx.x;
    const int bh = blockIdx.y;

    __half* const Pw = smh + 2 * KS_H + 2 * VT_H + warp * P_H;

    const __half* Qb  = g_Q + ((size_t)bh * SEQ + qt * 128) * 64;
    const __half* Kb  = g_K + (size_t)bh * SEQ * 64;
    const __half* Vtb = g_V + (size_t)bh * 64 * SEQ;

    unsigned Qf[4][2][4];
    const int qr = warp * 32;
#pragma unroll
    for (int dq = 0; dq < 4; dq++)
#pragma unroll
        for (int mt = 0; mt < 2; mt++) {
            int r0 = qr + mt * 16 + g;
            Qf[dq][mt][0] = *(const unsigned*)(Qb + r0       * 64 + dq * 16 + 2 * tt);
            Qf[dq][mt][1] = *(const unsigned*)(Qb + (r0 + 8) * 64 + dq * 16 + 2 * tt);
            Qf[dq][mt][2] = *(const unsigned*)(Qb + r0       * 64 + dq * 16 + 8 + 2 * tt);
            Qf[dq][mt][3] = *(const unsigned*)(Qb + (r0 + 8) * 64 + dq * 16 + 8 + 2 * tt);
        }

    float Of[2][8][4];
#pragma unroll
    for (int mt = 0; mt < 2; mt++)
#pragma unroll
        for (int nt = 0; nt < 8; nt++)
#pragma unroll
            for (int i = 0; i < 4; i++) Of[mt][nt][i] = 0.f;
    float mrow[2][2] = {{-1e30f, -1e30f}, {-1e30f, -1e30f}};
    float lrow[2][2] = {{0.f, 0.f}, {0.f, 0.f}};

    const int a_row  = (lane & 7) + ((lane & 8) ? 8 : 0);
    const int a_col8 = (lane & 16) ? 8 : 0;
    const int b_row  = (lane & 7) + ((lane & 16) ? 8 : 0);
    const int b_col8 = (lane & 8) ? 8 : 0;

    {
#pragma unroll
        for (int l = 0; l < 8; l++) {
            int s = t + 128 * l;
            int kr = s >> 3, kc = (s & 7) * 8;
            cp16(&Ksm0[kr * KPH + kc], Kb + (size_t)kr * 64 + kc);
            int vr = s >> 4, vc = (s & 15) * 8;
            cp16(&Vsm0[vr * VPH + vc], Vtb + (size_t)vr * SEQ + vc);
        }
        cp_commit();
    }

    for (int kt = 0; kt < SEQ / 128; kt++) {
        __half* const Kcur = (kt & 1) ? Ksm1 : Ksm0;
        __half* const Vcur = (kt & 1) ? Vsm1 : Vsm0;
        __half* const Knxt = (kt & 1) ? Ksm0 : Ksm1;
        __half* const Vnxt = (kt & 1) ? Vsm0 : Vsm1;

        cp_wait<0>();
        __syncthreads();

        if (kt < SEQ / 128 - 1) {
            const __half* Kp = Kb + (size_t)(kt + 1) * 128 * 64;
            const __half* Vp = Vtb + (kt + 1) * 128;
#pragma unroll
            for (int l = 0; l < 8; l++) {
                int s = t + 128 * l;
                int kr = s >> 3, kc = (s & 7) * 8;
                cp16(&Knxt[kr * KPH + kc], Kp + (size_t)kr * 64 + kc);
                int vr = s >> 4, vc = (s & 15) * 8;
                cp16(&Vnxt[vr * VPH + vc], Vp + (size_t)vr * SEQ + vc);
            }
            cp_commit();
        }

#pragma unroll
        for (int hf = 0; hf < 2; hf++) {
            const int hk = hf * 64;

            float sf[2][8][4];
#pragma unroll
            for (int mt = 0; mt < 2; mt++)
#pragma unroll
                for (int nt = 0; nt < 8; nt++)
#pragma unroll
                    for (int i = 0; i < 4; i++) sf[mt][nt][i] = 0.f;

#pragma unroll
            for (int dq = 0; dq < 4; dq++) {
                unsigned b[8][2];
#pragma unroll
                for (int np = 0; np < 4; np++)
                    ldsm4(b[np * 2][0], b[np * 2][1], b[np * 2 + 1][0], b[np * 2 + 1][1],
                          &Kcur[(hk + np * 16 + b_row) * KPH + dq * 16 + b_col8]);
#pragma unroll
                for (int mt = 0; mt < 2; mt++)
#pragma unroll
                    for (int nt = 0; nt < 8; nt++)
                        mma16(sf[mt][nt], Qf[dq][mt][0], Qf[dq][mt][1],
                              Qf[dq][mt][2], Qf[dq][mt][3], b[nt][0], b[nt][1]);
            }

#pragma unroll
            for (int mt = 0; mt < 2; mt++) {
                float alpha[2];
#pragma unroll
                for (int rp = 0; rp < 2; rp++) {
                    float mx = -1e30f;
#pragma unroll
                    for (int nt = 0; nt < 8; nt++)
                        mx = fmaxf(mx, fmaxf(sf[mt][nt][rp * 2], sf[mt][nt][rp * 2 + 1]));
                    mx = fmaxf(mx, __shfl_xor_sync(0xffffffffu, mx, 1));
                    mx = fmaxf(mx, __shfl_xor_sync(0xffffffffu, mx, 2));
                    float nm = fmaxf(mrow[mt][rp], mx);
                    float sum = 0.f;
#pragma unroll
                    for (int nt = 0; nt < 8; nt++) {
                        float p0 = exp2f(sf[mt][nt][rp * 2]     - nm);
                        float p1 = exp2f(sf[mt][nt][rp * 2 + 1] - nm);
                        sf[mt][nt][rp * 2] = p0; sf[mt][nt][rp * 2 + 1] = p1;
                        sum += p0 + p1;
                    }
                    sum += __shfl_xor_sync(0xffffffffu, sum, 1);
                    sum += __shfl_xor_sync(0xffffffffu, sum, 2);
                    alpha[rp] = exp2f(mrow[mt][rp] - nm);
                    mrow[mt][rp] = nm;
                    lrow[mt][rp] = lrow[mt][rp] * alpha[rp] + sum;
                }
#pragma unroll
                for (int nt = 0; nt < 8; nt++) {
                    Of[mt][nt][0] *= alpha[0]; Of[mt][nt][1] *= alpha[0];
                    Of[mt][nt][2] *= alpha[1]; Of[mt][nt][3] *= alpha[1];
                }
            }

            __syncwarp();
#pragma unroll
            for (int mt = 0; mt < 2; mt++)
#pragma unroll
                for (int nt = 0; nt < 8; nt++) {
                    __half2 h0 = __floats2half2_rn(sf[mt][nt][0], sf[mt][nt][1]);
                    __half2 h1 = __floats2half2_rn(sf[mt][nt][2], sf[mt][nt][3]);
                    *(__half2*)&Pw[(mt * 16 + g)     * PPH + nt * 8 + 2 * tt] = h0;
                    *(__half2*)&Pw[(mt * 16 + g + 8) * PPH + nt * 8 + 2 * tt] = h1;
                }
            __syncwarp();

#pragma unroll
            for (int kq = 0; kq < 4; kq++) {
                unsigned a[2][4];
#pragma unroll
                for (int mt = 0; mt < 2; mt++)
                    ldsm4(a[mt][0], a[mt][1], a[mt][2], a[mt][3],
                          &Pw[(mt * 16 + a_row) * PPH + kq * 16 + a_col8]);
                unsigned vb[8][2];
#pragma unroll
                for (int np = 0; np < 4; np++)
                    ldsm4(vb[np * 2][0], vb[np * 2][1], vb[np * 2 + 1][0], vb[np * 2 + 1][1],
                          &Vcur[(np * 16 + b_row) * VPH + hk + kq * 16 + b_col8]);
#pragma unroll
                for (int mt = 0; mt < 2; mt++)
#pragma unroll
                    for (int nt = 0; nt < 8; nt++)
                        mma16(Of[mt][nt], a[mt][0], a[mt][1], a[mt][2], a[mt][3],
                              vb[nt][0], vb[nt][1]);
            }
        }
        __syncthreads();
    }

    const int b = bh >> 4, h = bh & 15;
#pragma unroll
    for (int mt = 0; mt < 2; mt++) {
        const float inv0 = 1.f / lrow[mt][0], inv1 = 1.f / lrow[mt][1];
        const int row = qt * 128 + warp * 32 + mt * 16 + g;
#pragma unroll
        for (int nt = 0; nt < 8; nt++) {
            size_t base  = ((size_t)(b * SEQ + row))     * D_MODEL + h * 64 + nt * 8 + 2 * tt;
            size_t base2 = ((size_t)(b * SEQ + row + 8)) * D_MODEL + h * 64 + nt * 8 + 2 * tt;
            *(__half2*)&g_ctx[base]  = __floats2half2_rn(Of[mt][nt][0] * inv0,
                                                         Of[mt][nt][1] * inv0);
            *(__half2*)&g_ctx[base2] = __floats2half2_rn(Of[mt][nt][2] * inv1,
                                                         Of[mt][nt][3] * inv1);
        }
    }
}

extern "C" void kernel_launch(void* const* d_in, const int* in_sizes, int n_in,
                              void* d_out, int out_size)
{
    const float* query = (const float*)d_in[0];
    const float* key   = (const float*)d_in[1];
    const float* value = (const float*)d_in[2];
    const float* Wq    = (const float*)d_in[3];
    const float* bq    = (const float*)d_in[4];
    const float* Wk    = (const float*)d_in[5];
    const float* bk    = (const float*)d_in[6];
    const float* Wv    = (const float*)d_in[7];
    const float* bv    = (const float*)d_in[8];
    const float* Wo    = (const float*)d_in[9];
    const float* bo    = (const float*)d_in[10];
    float* out = (float*)d_out;

    __half *hq, *hk, *hv, *hwq, *hwk, *hwv, *hwo, *gQ, *gK, *gV, *gC;
    cudaGetSymbolAddress((void**)&hq,  h_q);
    cudaGetSymbolAddress((void**)&hk,  h_k);
    cudaGetSymbolAddress((void**)&hv,  h_v);
    cudaGetSymbolAddress((void**)&hwq, h_wq);
    cudaGetSymbolAddress((void**)&hwk, h_wk);
    cudaGetSymbolAddress((void**)&hwv, h_wv);
    cudaGetSymbolAddress((void**)&hwo, h_wo);
    cudaGetSymbolAddress((void**)&gQ,  g_Q);
    cudaGetSymbolAddress((void**)&gK,  g_K);
    cudaGetSymbolAddress((void**)&gV,  g_V);
    cudaGetSymbolAddress((void**)&gC,  g_ctx);

    cudaFuncSetAttribute(attn_f16, cudaFuncAttributeMaxDynamicSharedMemorySize,
                         ATTN_SMEM_BYTES);
    cudaFuncSetAttribute(gemm_f16p, cudaFuncAttributeMaxDynamicSharedMemorySize,
                         GEMM_SMEM_BYTES);

    // 1) convert everything to fp16 (one launch)
    CvtJobs cj;
    cj.src[0] = query; cj.dst[0] = hq;  cj.n[0] = MTOT * D_MODEL;
    cj.src[1] = key;   cj.dst[1] = hk;  cj.n[1] = MTOT * D_MODEL;
    cj.src[2] = value; cj.dst[2] = hv;  cj.n[2] = MTOT * D_MODEL;
    cj.src[3] = Wq;    cj.dst[3] = hwq; cj.n[3] = D_MODEL * D_MODEL;
    cj.src[4] = Wk;    cj.dst[4] = hwk; cj.n[4] = D_MODEL * D_MODEL;
    cj.src[5] = Wv;    cj.dst[5] = hwv; cj.n[5] = D_MODEL * D_MODEL;
    cj.src[6] = Wo;    cj.dst[6] = hwo; cj.n[6] = D_MODEL * D_MODEL;
    cvt_f16<<<dim3(MTOT * D_MODEL / (256 * 8), 7), 256>>>(cj);

    // 2) fused Q/K/V projections
    GemmJobs3 qkv;
    qkv.j[0] = { hq, hwq, bq, gQ, 1, 0.125f * LOG2E };
    qkv.j[1] = { hk, hwk, bk, gK, 1, 1.0f };
    qkv.j[2] = { hv, hwv, bv, gV, 2, 1.0f };
    gemm_f16p<<<dim3(MTOT / 128, D_MODEL / 128, 3), 256, GEMM_SMEM_BYTES>>>(qkv);

    // 3) attention (Br=128, 4 warps x 32 q rows)
    dim3 agrid(SEQ / 128, BATCH * NUM_HEADS);
    attn_f16<<<agrid, 128, ATTN_SMEM_BYTES>>>();

    // 4) output projection
    GemmJobs3 oj;
    oj.j[0] = { gC, hwo, bo, out, 0, 1.0f };
    oj.j[1] = oj.j[0]; oj.j[2] = oj.j[0];
    gemm_f16p<<<dim3(MTOT / 128, D_MODEL / 128, 1), 256, GEMM_SMEM_BYTES>>>(oj);
}

// round 17
// speedup vs baseline: 1.4982x; 1.0004x over previous
#include <cuda_runtime.h>
#include <cuda_fp16.h>
#include <cstdint>

#define D_MODEL   1024
#define NUM_HEADS 16
#define SEQ       2048
#define BATCH     2
#define MTOT      (BATCH*SEQ)   /* 4096 */
#define LOG2E     1.4426950408889634f

// Scratch (allocation-free rule: __device__ globals).
__device__ __half h_q[(size_t)MTOT * D_MODEL];
__device__ __half h_k[(size_t)MTOT * D_MODEL];
__device__ __half h_v[(size_t)MTOT * D_MODEL];
__device__ __half h_wq[(size_t)D_MODEL * D_MODEL];
__device__ __half h_wk[(size_t)D_MODEL * D_MODEL];
__device__ __half h_wv[(size_t)D_MODEL * D_MODEL];
__device__ __half h_wo[(size_t)D_MODEL * D_MODEL];
__device__ __half g_Q[(size_t)MTOT * D_MODEL];   // [b,h,s,d], pre-scaled by 0.125*log2e
__device__ __half g_K[(size_t)MTOT * D_MODEL];   // [b,h,s,d]
__device__ __half g_V[(size_t)MTOT * D_MODEL];   // TRANSPOSED [b,h,d,s]
__device__ __half g_ctx[(size_t)MTOT * D_MODEL]; // [m, D_MODEL] fp16

__device__ __forceinline__ void ldsm4(unsigned& r0, unsigned& r1, unsigned& r2, unsigned& r3,
                                      const void* p) {
    unsigned a = (unsigned)__cvta_generic_to_shared(p);
    asm volatile("ldmatrix.sync.aligned.m8n8.x4.shared.b16 {%0,%1,%2,%3}, [%4];"
                 : "=r"(r0), "=r"(r1), "=r"(r2), "=r"(r3) : "r"(a));
}
__device__ __forceinline__ void mma16(float* c, unsigned a0, unsigned a1, unsigned a2, unsigned a3,
                                      unsigned b0, unsigned b1) {
    asm volatile("mma.sync.aligned.m16n8k16.row.col.f32.f16.f16.f32 "
                 "{%0,%1,%2,%3},{%4,%5,%6,%7},{%8,%9},{%0,%1,%2,%3};"
                 : "+f"(c[0]), "+f"(c[1]), "+f"(c[2]), "+f"(c[3])
                 : "r"(a0), "r"(a1), "r"(a2), "r"(a3), "r"(b0), "r"(b1));
}
__device__ __forceinline__ void cp16(void* smem_dst, const void* gsrc) {
    unsigned d = (unsigned)__cvta_generic_to_shared(smem_dst);
    asm volatile("cp.async.cg.shared.global [%0], [%1], 16;\n" :: "r"(d), "l"(gsrc));
}
__device__ __forceinline__ void cp16ca(void* smem_dst, const void* gsrc) {
    unsigned d = (unsigned)__cvta_generic_to_shared(smem_dst);
    asm volatile("cp.async.ca.shared.global [%0], [%1], 16;\n" :: "r"(d), "l"(gsrc));
}
__device__ __forceinline__ void cp_commit() { asm volatile("cp.async.commit_group;\n"); }
template <int N> __device__ __forceinline__ void cp_wait() {
    asm volatile("cp.async.wait_group %0;\n" :: "n"(N));
}

// ------------------------- fp32 -> fp16 conversion (7 tensors, one launch) ----
struct CvtJobs { const float* src[7]; __half* dst[7]; int n[7]; };

__global__ __launch_bounds__(256) void cvt_f16(CvtJobs jobs)
{
    int j = blockIdx.y;
    int base = (blockIdx.x * 256 + threadIdx.x) * 8;
    if (base >= jobs.n[j]) return;
    const float4* s = (const float4*)(jobs.src[j] + base);
    float4 v0 = s[0], v1 = s[1];
    __half2 p0 = __floats2half2_rn(v0.x, v0.y);
    __half2 p1 = __floats2half2_rn(v0.z, v0.w);
    __half2 p2 = __floats2half2_rn(v1.x, v1.y);
    __half2 p3 = __floats2half2_rn(v1.z, v1.w);
    uint4 u; u.x = *(unsigned*)&p0; u.y = *(unsigned*)&p1;
    u.z = *(unsigned*)&p2; u.w = *(unsigned*)&p3;
    *(uint4*)(jobs.dst[j] + base) = u;
}

// ------------------------- fp16 GEMM, 4-stage cp.async pipeline (round-11) -----
#define KGP 40
#define GSTG (128 * KGP)
#define GSTAGE_H (2 * GSTG)
#define NSTAGE 4
#define GEMM_SMEM_BYTES (NSTAGE * GSTAGE_H * 2)   /* 81920 */

struct GemmJob { const __half* A; const __half* W; const float* bias;
                 void* C; int mode; float oscale; };
struct GemmJobs3 { GemmJob j[3]; };

__global__ __launch_bounds__(256, 2) void gemm_f16p(GemmJobs3 js)
{
    extern __shared__ __half sg[];
    const GemmJob jb = js.j[blockIdx.z];
    const int t = threadIdx.x, lane = t & 31, warp = t >> 5;
    const int wm = warp >> 1, wn = warp & 1;
    const int g = lane >> 2, tt = lane & 3;
    const int bm = blockIdx.x, bn = blockIdx.y;

    float acc[2][8][4];
#pragma unroll
    for (int mt = 0; mt < 2; mt++)
#pragma unroll
        for (int nt = 0; nt < 8; nt++)
#pragma unroll
            for (int i = 0; i < 4; i++) acc[mt][nt][i] = 0.f;

    const __half* Ap = jb.A + (size_t)bm * 128 * 1024;
    const __half* Wp = jb.W + (size_t)bn * 128 * 1024;

    const int a_row  = (lane & 7) + ((lane & 8) ? 8 : 0);
    const int a_col8 = (lane & 16) ? 8 : 0;
    const int b_row  = (lane & 7) + ((lane & 16) ? 8 : 0);
    const int b_col8 = (lane & 8) ? 8 : 0;

    const int fm0 = t >> 2, fc0 = (t & 3) * 8;
    const int fm1 = (t + 256) >> 2, fc1 = ((t + 256) & 3) * 8;

#pragma unroll
    for (int st = 0; st < 3; st++) {
        __half* Sa = sg + st * GSTAGE_H;
        __half* Sb = Sa + GSTG;
        int k0 = st * 32;
        cp16(&Sa[fm0 * KGP + fc0], Ap + (size_t)fm0 * 1024 + k0 + fc0);
        cp16(&Sa[fm1 * KGP + fc1], Ap + (size_t)fm1 * 1024 + k0 + fc1);
        cp16ca(&Sb[fm0 * KGP + fc0], Wp + (size_t)fm0 * 1024 + k0 + fc0);
        cp16ca(&Sb[fm1 * KGP + fc1], Wp + (size_t)fm1 * 1024 + k0 + fc1);
        cp_commit();
    }

    for (int ks = 0; ks < 32; ks++) {
        cp_wait<2>();
        __syncthreads();

        if (ks + 3 < 32) {
            int st = (ks + 3) & 3;
            __half* Sa = sg + st * GSTAGE_H;
            __half* Sb = Sa + GSTG;
            int k0 = (ks + 3) * 32;
            cp16(&Sa[fm0 * KGP + fc0], Ap + (size_t)fm0 * 1024 + k0 + fc0);
            cp16(&Sa[fm1 * KGP + fc1], Ap + (size_t)fm1 * 1024 + k0 + fc1);
            cp16ca(&Sb[fm0 * KGP + fc0], Wp + (size_t)fm0 * 1024 + k0 + fc0);
            cp16ca(&Sb[fm1 * KGP + fc1], Wp + (size_t)fm1 * 1024 + k0 + fc1);
        }
        cp_commit();

        __half* Sa = sg + (ks & 3) * GSTAGE_H;
        __half* Sb = Sa + GSTG;
#pragma unroll
        for (int kq = 0; kq < 32; kq += 16) {
            unsigned a[2][4];
#pragma unroll
            for (int mt = 0; mt < 2; mt++) {
                int base = wm * 32 + mt * 16;
                ldsm4(a[mt][0], a[mt][1], a[mt][2], a[mt][3],
                      &Sa[(base + a_row) * KGP + kq + a_col8]);
            }
            unsigned b[8][2];
#pragma unroll
            for (int np = 0; np < 4; np++) {
                int nb = wn * 64 + np * 16;
                ldsm4(b[np * 2][0], b[np * 2][1], b[np * 2 + 1][0], b[np * 2 + 1][1],
                      &Sb[(nb + b_row) * KGP + kq + b_col8]);
            }
#pragma unroll
            for (int mt = 0; mt < 2; mt++)
#pragma unroll
                for (int nt = 0; nt < 8; nt++)
                    mma16(acc[mt][nt], a[mt][0], a[mt][1], a[mt][2], a[mt][3],
                          b[nt][0], b[nt][1]);
        }
    }

#pragma unroll
    for (int mt = 0; mt < 2; mt++) {
        int row0 = bm * 128 + wm * 32 + mt * 16 + g;
#pragma unroll
        for (int nt = 0; nt < 8; nt++) {
            int cc = bn * 128 + wn * 64 + nt * 8 + 2 * tt;
            float2 bb = *(const float2*)&jb.bias[cc];
#pragma unroll
            for (int rp = 0; rp < 2; rp++) {
                int row = row0 + rp * 8;
                float2 v;
                v.x = acc[mt][nt][rp * 2 + 0] + bb.x;
                v.y = acc[mt][nt][rp * 2 + 1] + bb.y;
                int b = row >> 11, sq = row & (SEQ - 1);
                int h = cc >> 6, dd = cc & 63;
                if (jb.mode == 1) {
                    __half* C = (__half*)jb.C;
                    __half2 hv = __floats2half2_rn(v.x * jb.oscale, v.y * jb.oscale);
                    *(__half2*)&C[((size_t)((b * NUM_HEADS + h) * SEQ + sq) << 6) + dd] = hv;
                } else if (jb.mode == 2) {
                    __half* C = (__half*)jb.C;
                    size_t base = (size_t)((b * NUM_HEADS + h) * 64 + dd) * SEQ + sq;
                    C[base] = __float2half_rn(v.x);
                    C[base + SEQ] = __float2half_rn(v.y);
                } else {
                    float* C = (float*)jb.C;
                    *(float2*)&C[(size_t)row * D_MODEL + cc] = v;
                }
            }
        }
    }
}

// ------------------------- flash attention, fp16 mma (round-11) ---------------
// 128 threads (4 warps), warp owns 32 q rows (2 m-frags) -> Br=128, 2 CTAs/SM.
#define KPH 72
#define VPH 136
#define PPH 72
#define KS_H (128 * KPH)
#define VT_H (64 * VPH)
#define P_H  (32 * PPH)
#define ATTN_SMEM_BYTES ((2 * KS_H + 2 * VT_H + 4 * P_H) * 2)  /* 90112 */

__global__ __launch_bounds__(128, 2) void attn_f16()
{
    extern __shared__ __half smh[];
    __half* const Ksm0 = smh;
    __half* const Ksm1 = smh + KS_H;
    __half* const Vsm0 = smh + 2 * KS_H;
    __half* const Vsm1 = smh + 2 * KS_H + VT_H;

    const int t = threadIdx.x, lane = t & 31, warp = t >> 5;
    const int g = lane >> 2, tt = lane & 3;
    const int qt = blockIdx.x;
    const int bh = blockIdx.y;

    __half* const Pw = smh + 2 * KS_H + 2 * VT_H + warp * P_H;

    const __half* Qb  = g_Q + ((size_t)bh * SEQ + qt * 128) * 64;
    const __half* Kb  = g_K + (size_t)bh * SEQ * 64;
    const __half* Vtb = g_V + (size_t)bh * 64 * SEQ;

    unsigned Qf[4][2][4];
    const int qr = warp * 32;
#pragma unroll
    for (int dq = 0; dq < 4; dq++)
#pragma unroll
        for (int mt = 0; mt < 2; mt++) {
            int r0 = qr + mt * 16 + g;
            Qf[dq][mt][0] = *(const unsigned*)(Qb + r0       * 64 + dq * 16 + 2 * tt);
            Qf[dq][mt][1] = *(const unsigned*)(Qb + (r0 + 8) * 64 + dq * 16 + 2 * tt);
            Qf[dq][mt][2] = *(const unsigned*)(Qb + r0       * 64 + dq * 16 + 8 + 2 * tt);
            Qf[dq][mt][3] = *(const unsigned*)(Qb + (r0 + 8) * 64 + dq * 16 + 8 + 2 * tt);
        }

    float Of[2][8][4];
#pragma unroll
    for (int mt = 0; mt < 2; mt++)
#pragma unroll
        for (int nt = 0; nt < 8; nt++)
#pragma unroll
            for (int i = 0; i < 4; i++) Of[mt][nt][i] = 0.f;
    float mrow[2][2] = {{-1e30f, -1e30f}, {-1e30f, -1e30f}};
    float lrow[2][2] = {{0.f, 0.f}, {0.f, 0.f}};

    const int a_row  = (lane & 7) + ((lane & 8) ? 8 : 0);
    const int a_col8 = (lane & 16) ? 8 : 0;
    const int b_row  = (lane & 7) + ((lane & 16) ? 8 : 0);
    const int b_col8 = (lane & 8) ? 8 : 0;

    {
#pragma unroll
        for (int l = 0; l < 8; l++) {
            int s = t + 128 * l;
            int kr = s >> 3, kc = (s & 7) * 8;
            cp16(&Ksm0[kr * KPH + kc], Kb + (size_t)kr * 64 + kc);
            int vr = s >> 4, vc = (s & 15) * 8;
            cp16(&Vsm0[vr * VPH + vc], Vtb + (size_t)vr * SEQ + vc);
        }
        cp_commit();
    }

    for (int kt = 0; kt < SEQ / 128; kt++) {
        __half* const Kcur = (kt & 1) ? Ksm1 : Ksm0;
        __half* const Vcur = (kt & 1) ? Vsm1 : Vsm0;
        __half* const Knxt = (kt & 1) ? Ksm0 : Ksm1;
        __half* const Vnxt = (kt & 1) ? Vsm0 : Vsm1;

        cp_wait<0>();
        __syncthreads();

        if (kt < SEQ / 128 - 1) {
            const __half* Kp = Kb + (size_t)(kt + 1) * 128 * 64;
            const __half* Vp = Vtb + (kt + 1) * 128;
#pragma unroll
            for (int l = 0; l < 8; l++) {
                int s = t + 128 * l;
                int kr = s >> 3, kc = (s & 7) * 8;
                cp16(&Knxt[kr * KPH + kc], Kp + (size_t)kr * 64 + kc);
                int vr = s >> 4, vc = (s & 15) * 8;
                cp16(&Vnxt[vr * VPH + vc], Vp + (size_t)vr * SEQ + vc);
            }
            cp_commit();
        }

#pragma unroll
        for (int hf = 0; hf < 2; hf++) {
            const int hk = hf * 64;

            float sf[2][8][4];
#pragma unroll
            for (int mt = 0; mt < 2; mt++)
#pragma unroll
                for (int nt = 0; nt < 8; nt++)
#pragma unroll
                    for (int i = 0; i < 4; i++) sf[mt][nt][i] = 0.f;

#pragma unroll
            for (int dq = 0; dq < 4; dq++) {
                unsigned b[8][2];
#pragma unroll
                for (int np = 0; np < 4; np++)
                    ldsm4(b[np * 2][0], b[np * 2][1], b[np * 2 + 1][0], b[np * 2 + 1][1],
                          &Kcur[(hk + np * 16 + b_row) * KPH + dq * 16 + b_col8]);
#pragma unroll
                for (int mt = 0; mt < 2; mt++)
#pragma unroll
                    for (int nt = 0; nt < 8; nt++)
                        mma16(sf[mt][nt], Qf[dq][mt][0], Qf[dq][mt][1],
                              Qf[dq][mt][2], Qf[dq][mt][3], b[nt][0], b[nt][1]);
            }

#pragma unroll
            for (int mt = 0; mt < 2; mt++) {
                float alpha[2];
#pragma unroll
                for (int rp = 0; rp < 2; rp++) {
                    float mx = -1e30f;
#pragma unroll
                    for (int nt = 0; nt < 8; nt++)
                        mx = fmaxf(mx, fmaxf(sf[mt][nt][rp * 2], sf[mt][nt][rp * 2 + 1]));
                    mx = fmaxf(mx, __shfl_xor_sync(0xffffffffu, mx, 1));
                    mx = fmaxf(mx, __shfl_xor_sync(0xffffffffu, mx, 2));
                    float nm = fmaxf(mrow[mt][rp], mx);
                    float sum = 0.f;
#pragma unroll
                    for (int nt = 0; nt < 8; nt++) {
                        float p0 = exp2f(sf[mt][nt][rp * 2]     - nm);
                        float p1 = exp2f(sf[mt][nt][rp * 2 + 1] - nm);
                        sf[mt][nt][rp * 2] = p0; sf[mt][nt][rp * 2 + 1] = p1;
                        sum += p0 + p1;
                    }
                    sum += __shfl_xor_sync(0xffffffffu, sum, 1);
                    sum += __shfl_xor_sync(0xffffffffu, sum, 2);
                    alpha[rp] = exp2f(mrow[mt][rp] - nm);
                    mrow[mt][rp] = nm;
                    lrow[mt][rp] = lrow[mt][rp] * alpha[rp] + sum;
                }
#pragma unroll
                for (int nt = 0; nt < 8; nt++) {
                    Of[mt][nt][0] *= alpha[0]; Of[mt][nt][1] *= alpha[0];
                    Of[mt][nt][2] *= alpha[1]; Of[mt][nt][3] *= alpha[1];
                }
            }

            __syncwarp();
#pragma unroll
            for (int mt = 0; mt < 2; mt++)
#pragma unroll
                for (int nt = 0; nt < 8; nt++) {
                    __half2 h0 = __floats2half2_rn(sf[mt][nt][0], sf[mt][nt][1]);
                    __half2 h1 = __floats2half2_rn(sf[mt][nt][2], sf[mt][nt][3]);
                    *(__half2*)&Pw[(mt * 16 + g)     * PPH + nt * 8 + 2 * tt] = h0;
                    *(__half2*)&Pw[(mt * 16 + g + 8) * PPH + nt * 8 + 2 * tt] = h1;
                }
            __syncwarp();

#pragma unroll
            for (int kq = 0; kq < 4; kq++) {
                unsigned a[2][4];
#pragma unroll
                for (int mt = 0; mt < 2; mt++)
                    ldsm4(a[mt][0], a[mt][1], a[mt][2], a[mt][3],
                          &Pw[(mt * 16 + a_row) * PPH + kq * 16 + a_col8]);
                unsigned vb[8][2];
#pragma unroll
                for (int np = 0; np < 4; np++)
                    ldsm4(vb[np * 2][0], vb[np * 2][1], vb[np * 2 + 1][0], vb[np * 2 + 1][1],
                          &Vcur[(np * 16 + b_row) * VPH + hk + kq * 16 + b_col8]);
#pragma unroll
                for (int mt = 0; mt < 2; mt++)
#pragma unroll
                    for (int nt = 0; nt < 8; nt++)
                        mma16(Of[mt][nt], a[mt][0], a[mt][1], a[mt][2], a[mt][3],
                              vb[nt][0], vb[nt][1]);
            }
        }
        __syncthreads();
    }

    const int b = bh >> 4, h = bh & 15;
#pragma unroll
    for (int mt = 0; mt < 2; mt++) {
        const float inv0 = 1.f / lrow[mt][0], inv1 = 1.f / lrow[mt][1];
        const int row = qt * 128 + warp * 32 + mt * 16 + g;
#pragma unroll
        for (int nt = 0; nt < 8; nt++) {
            size_t base  = ((size_t)(b * SEQ + row))     * D_MODEL + h * 64 + nt * 8 + 2 * tt;
            size_t base2 = ((size_t)(b * SEQ + row + 8)) * D_MODEL + h * 64 + nt * 8 + 2 * tt;
            *(__half2*)&g_ctx[base]  = __floats2half2_rn(Of[mt][nt][0] * inv0,
                                                         Of[mt][nt][1] * inv0);
            *(__half2*)&g_ctx[base2] = __floats2half2_rn(Of[mt][nt][2] * inv1,
                                                         Of[mt][nt][3] * inv1);
        }
    }
}

extern "C" void kernel_launch(void* const* d_in, const int* in_sizes, int n_in,
                              void* d_out, int out_size)
{
    const float* query = (const float*)d_in[0];
    const float* key   = (const float*)d_in[1];
    const float* value = (const float*)d_in[2];
    const float* Wq    = (const float*)d_in[3];
    const float* bq    = (const float*)d_in[4];
    const float* Wk    = (const float*)d_in[5];
    const float* bk    = (const float*)d_in[6];
    const float* Wv    = (const float*)d_in[7];
    const float* bv    = (const float*)d_in[8];
    const float* Wo    = (const float*)d_in[9];
    const float* bo    = (const float*)d_in[10];
    float* out = (float*)d_out;

    __half *hq, *hk, *hv, *hwq, *hwk, *hwv, *hwo, *gQ, *gK, *gV, *gC;
    cudaGetSymbolAddress((void**)&hq,  h_q);
    cudaGetSymbolAddress((void**)&hk,  h_k);
    cudaGetSymbolAddress((void**)&hv,  h_v);
    cudaGetSymbolAddress((void**)&hwq, h_wq);
    cudaGetSymbolAddress((void**)&hwk, h_wk);
    cudaGetSymbolAddress((void**)&hwv, h_wv);
    cudaGetSymbolAddress((void**)&hwo, h_wo);
    cudaGetSymbolAddress((void**)&gQ,  g_Q);
    cudaGetSymbolAddress((void**)&gK,  g_K);
    cudaGetSymbolAddress((void**)&gV,  g_V);
    cudaGetSymbolAddress((void**)&gC,  g_ctx);

    cudaFuncSetAttribute(attn_f16, cudaFuncAttributeMaxDynamicSharedMemorySize,
                         ATTN_SMEM_BYTES);
    cudaFuncSetAttribute(gemm_f16p, cudaFuncAttributeMaxDynamicSharedMemorySize,
                         GEMM_SMEM_BYTES);

    // 1) convert everything to fp16 (one launch)
    CvtJobs cj;
    cj.src[0] = query; cj.dst[0] = hq;  cj.n[0] = MTOT * D_MODEL;
    cj.src[1] = key;   cj.dst[1] = hk;  cj.n[1] = MTOT * D_MODEL;
    cj.src[2] = value; cj.dst[2] = hv;  cj.n[2] = MTOT * D_MODEL;
    cj.src[3] = Wq;    cj.dst[3] = hwq; cj.n[3] = D_MODEL * D_MODEL;
    cj.src[4] = Wk;    cj.dst[4] = hwk; cj.n[4] = D_MODEL * D_MODEL;
    cj.src[5] = Wv;    cj.dst[5] = hwv; cj.n[5] = D_MODEL * D_MODEL;
    cj.src[6] = Wo;    cj.dst[6] = hwo; cj.n[6] = D_MODEL * D_MODEL;
    cvt_f16<<<dim3(MTOT * D_MODEL / (256 * 8), 7), 256>>>(cj);

    // 2) fused Q/K/V projections
    GemmJobs3 qkv;
    qkv.j[0] = { hq, hwq, bq, gQ, 1, 0.125f * LOG2E };
    qkv.j[1] = { hk, hwk, bk, gK, 1, 1.0f };
    qkv.j[2] = { hv, hwv, bv, gV, 2, 1.0f };
    gemm_f16p<<<dim3(MTOT / 128, D_MODEL / 128, 3), 256, GEMM_SMEM_BYTES>>>(qkv);

    // 3) attention (Br=128, 4 warps x 32 q rows)
    dim3 agrid(SEQ / 128, BATCH * NUM_HEADS);
    attn_f16<<<agrid, 128, ATTN_SMEM_BYTES>>>();

    // 4) output projection
    GemmJobs3 oj;
    oj.j[0] = { gC, hwo, bo, out, 0, 1.0f };
    oj.j[1] = oj.j[0]; oj.j[2] = oj.j[0];
    gemm_f16p<<<dim3(MTOT / 128, D_MODEL / 128, 1), 256, GEMM_SMEM_BYTES>>>(oj);
}